// round 1
// baseline (speedup 1.0000x reference)
#include <cuda_runtime.h>
#include <cstdint>

// GraphSAGE-style net, N=100000 nodes, K=32 neighbors, D=64.
// Fused pipeline:
//   per node n (one warp per node):
//     z[d]   = max over 33 vectors v of (v . aggr1_W[d])          (relu/bias folded out of max)
//     a[d]   = relu(z[d] + aggr1_b[d])
//     e      = l2norm(relu(a @ emb1_W^T))
//     y[d]   = relu(e @ aggr2_W^T + aggr2_b)[d]
//   global: g_ymax[d] = max_n y[n][d]   (== aggr2, since stage-2 max covers all rows)
//   tail:   out = reg(  l2norm(relu(g_ymax @ emb2_W^T))  )

#define NWARPS 12
#define TPB (NWARPS*32)
#define GRID 296

__device__ unsigned g_ymax[64];

__device__ __forceinline__ void ffma2(unsigned long long &acc, unsigned long long a, unsigned long long b){
    asm volatile("fma.rn.f32x2 %0, %1, %2, %0;" : "+l"(acc) : "l"(a), "l"(b));
}
__device__ __forceinline__ float hadd2(unsigned long long v){
    return __uint_as_float((unsigned)v) + __uint_as_float((unsigned)(v >> 32));
}

// shared-memory float offsets (rows padded to 68 floats -> conflict-free LDS.128)
#define W1OFF 0
#define WEOFF 4352
#define W2OFF 8704
#define B1OFF 13056
#define B2OFF 13120
#define VOFF  13184
#define SMEM_FLOATS (VOFF + NWARPS*2112)
#define SMEM_BYTES (SMEM_FLOATS*4)

__global__ void init_ymax(){
    if (threadIdx.x < 64) g_ymax[threadIdx.x] = 0u;   // relu => y>=0, so 0 is the max identity
}

__global__ __launch_bounds__(TPB, 1)
void sage_main(const float* __restrict__ xs, const float* __restrict__ xn,
               const float* __restrict__ W1, const float* __restrict__ b1,
               const float* __restrict__ WE,
               const float* __restrict__ W2a, const float* __restrict__ b2a,
               int nNodes)
{
    extern __shared__ float sm[];
    int tid = threadIdx.x;

    // Load all three 64x64 weight matrices into SMEM, padded row stride 68.
    for (int idx = tid; idx < 4096; idx += TPB){
        int r = idx >> 6, c = idx & 63;
        sm[W1OFF + r*68 + c] = W1[idx];
        sm[WEOFF + r*68 + c] = WE[idx];
        sm[W2OFF + r*68 + c] = W2a[idx];
    }
    if (tid < 64){ sm[B1OFF + tid] = b1[tid]; sm[B2OFF + tid] = b2a[tid]; }
    __syncthreads();

    int lane = tid & 31, wid = tid >> 5;
    float* Vw = sm + VOFF + wid*2112;      // per-warp staging: 33 vectors x 64 floats
    float4* V4 = (float4*)Vw;

    const float* Wt  = sm + W1OFF + lane*68;
    const float* Wt2 = sm + W1OFF + (lane+32)*68;
    const float* Et  = sm + WEOFF + lane*68;
    const float* Et2 = sm + WEOFF + (lane+32)*68;
    const float* Ct  = sm + W2OFF + lane*68;
    const float* Ct2 = sm + W2OFF + (lane+32)*68;
    float bA = sm[B1OFF + lane], bB = sm[B1OFF + lane + 32];
    float cA = sm[B2OFF + lane], cB = sm[B2OFF + lane + 32];

    float gymA = 0.f, gymB = 0.f;
    int gw = blockIdx.x*NWARPS + wid;
    int gstride = gridDim.x*NWARPS;

    for (int n = gw; n < nNodes; n += gstride){
        // ---- stage: V[0]=self, V[1..32]=neighbors (coalesced float4) ----
        const float4* sp = (const float4*)(xs + (long long)n*64);
        const float4* np = (const float4*)(xn + (long long)n*2048);
        for (int u = lane; u < 528; u += 32){
            V4[u] = (u < 16) ? sp[u] : np[u - 16];
        }
        __syncwarp();

        // ---- phase A: z[d] = max_k (v_k . W1[d]), lane owns dims (lane, lane+32) ----
        float mA = -3.402823466e38f, mB = -3.402823466e38f;
        #pragma unroll 1
        for (int kc = 0; kc < 32; kc += 8){
            unsigned long long aA[8], aB[8];
            #pragma unroll
            for (int j = 0; j < 8; j++){ aA[j] = 0ull; aB[j] = 0ull; }
            const float* vbase = Vw + kc*64;
            #pragma unroll 4
            for (int i = 0; i < 64; i += 4){
                ulonglong2 wa = *(const ulonglong2*)(Wt  + i);
                ulonglong2 wb = *(const ulonglong2*)(Wt2 + i);
                #pragma unroll
                for (int j = 0; j < 8; j++){
                    ulonglong2 vv = *(const ulonglong2*)(vbase + j*64 + i);
                    ffma2(aA[j], vv.x, wa.x);
                    ffma2(aA[j], vv.y, wa.y);
                    ffma2(aB[j], vv.x, wb.x);
                    ffma2(aB[j], vv.y, wb.y);
                }
            }
            #pragma unroll
            for (int j = 0; j < 8; j++){
                mA = fmaxf(mA, hadd2(aA[j]));
                mB = fmaxf(mB, hadd2(aB[j]));
            }
        }
        {   // tail vector k=32
            unsigned long long aA = 0ull, aB = 0ull;
            const float* vbase = Vw + 32*64;
            #pragma unroll 4
            for (int i = 0; i < 64; i += 4){
                ulonglong2 wa = *(const ulonglong2*)(Wt  + i);
                ulonglong2 wb = *(const ulonglong2*)(Wt2 + i);
                ulonglong2 vv = *(const ulonglong2*)(vbase + i);
                ffma2(aA, vv.x, wa.x); ffma2(aA, vv.y, wa.y);
                ffma2(aB, vv.x, wb.x); ffma2(aB, vv.y, wb.y);
            }
            mA = fmaxf(mA, hadd2(aA));
            mB = fmaxf(mB, hadd2(aB));
        }

        // a = relu(z + b1), broadcast via SMEM row 0
        float aAv = fmaxf(mA + bA, 0.f);
        float aBv = fmaxf(mB + bB, 0.f);
        __syncwarp();
        Vw[lane] = aAv; Vw[lane + 32] = aBv;
        __syncwarp();

        // ---- phase B: e = relu(a @ emb1_W^T), then l2 normalize ----
        unsigned long long eA = 0ull, eB = 0ull;
        #pragma unroll
        for (int i = 0; i < 64; i += 4){
            ulonglong2 wa = *(const ulonglong2*)(Et  + i);
            ulonglong2 wb = *(const ulonglong2*)(Et2 + i);
            ulonglong2 vv = *(const ulonglong2*)(Vw + i);
            ffma2(eA, vv.x, wa.x); ffma2(eA, vv.y, wa.y);
            ffma2(eB, vv.x, wb.x); ffma2(eB, vv.y, wb.y);
        }
        float eAf = fmaxf(hadd2(eA), 0.f);
        float eBf = fmaxf(hadd2(eB), 0.f);
        float ss = eAf*eAf + eBf*eBf;
        #pragma unroll
        for (int off = 16; off > 0; off >>= 1) ss += __shfl_xor_sync(0xffffffffu, ss, off);
        float nrm = sqrtf(ss);
        float inv = (nrm > 0.f) ? (1.f/nrm) : 0.f;   // nrm==0 => e is all zero anyway
        __syncwarp();
        Vw[lane] = eAf*inv; Vw[lane + 32] = eBf*inv;
        __syncwarp();

        // ---- phase C: y = relu(en @ aggr2_W^T + b2), fold into per-warp running max ----
        unsigned long long yA = 0ull, yB = 0ull;
        #pragma unroll
        for (int i = 0; i < 64; i += 4){
            ulonglong2 wa = *(const ulonglong2*)(Ct  + i);
            ulonglong2 wb = *(const ulonglong2*)(Ct2 + i);
            ulonglong2 vv = *(const ulonglong2*)(Vw + i);
            ffma2(yA, vv.x, wa.x); ffma2(yA, vv.y, wa.y);
            ffma2(yB, vv.x, wb.x); ffma2(yB, vv.y, wb.y);
        }
        float yAf = fmaxf(hadd2(yA) + cA, 0.f);
        float yBf = fmaxf(hadd2(yB) + cB, 0.f);
        gymA = fmaxf(gymA, yAf);
        gymB = fmaxf(gymB, yBf);
        __syncwarp();
    }

    // nonneg floats: uint compare == float compare
    atomicMax(&g_ymax[lane],      __float_as_uint(gymA));
    atomicMax(&g_ymax[lane + 32], __float_as_uint(gymB));
}

__global__ void sage_final(const float* __restrict__ E2, const float* __restrict__ RW1,
                           const float* __restrict__ Rb1, const float* __restrict__ RW2,
                           const float* __restrict__ Rb2, float* __restrict__ out)
{
    __shared__ float a2[64], t2[64], hs[64];
    __shared__ float sinv;
    int d = threadIdx.x;
    a2[d] = __uint_as_float(g_ymax[d]);     // == aggr2 (already relu'd max)
    __syncthreads();
    float s = 0.f;
    #pragma unroll
    for (int i = 0; i < 64; i++) s += a2[i]*E2[d*64 + i];
    s = fmaxf(s, 0.f);
    t2[d] = s;
    __syncthreads();
    if (d == 0){
        float acc = 0.f;
        for (int i = 0; i < 64; i++) acc += t2[i]*t2[i];
        float nr = sqrtf(acc);
        sinv = (nr > 0.f) ? (1.f/nr) : 0.f;
    }
    __syncthreads();
    a2[d] = t2[d]*sinv;                     // emb2
    __syncthreads();
    float h = Rb1[d];
    #pragma unroll
    for (int i = 0; i < 64; i++) h += a2[i]*RW1[d*64 + i];
    h = fmaxf(h, 0.f);
    hs[d] = h;
    __syncthreads();
    if (d == 0){
        float o = Rb2[0];
        for (int i = 0; i < 64; i++) o += hs[i]*RW2[i];
        out[0] = o;
    }
}

extern "C" void kernel_launch(void* const* d_in, const int* in_sizes, int n_in,
                              void* d_out, int out_size)
{
    const float* xs  = (const float*)d_in[0];
    const float* xn  = (const float*)d_in[1];
    const float* W1  = (const float*)d_in[2];
    const float* b1  = (const float*)d_in[3];
    const float* WE  = (const float*)d_in[4];
    const float* W2a = (const float*)d_in[5];
    const float* b2a = (const float*)d_in[6];
    const float* E2  = (const float*)d_in[7];
    const float* RW1 = (const float*)d_in[8];
    const float* Rb1 = (const float*)d_in[9];
    const float* RW2 = (const float*)d_in[10];
    const float* Rb2 = (const float*)d_in[11];
    int nNodes = in_sizes[0] / 64;

    cudaFuncSetAttribute(sage_main, cudaFuncAttributeMaxDynamicSharedMemorySize, SMEM_BYTES);
    init_ymax<<<1, 64>>>();
    sage_main<<<GRID, TPB, SMEM_BYTES>>>(xs, xn, W1, b1, WE, W2a, b2a, nNodes);
    sage_final<<<1, 64>>>(E2, RW1, Rb1, RW2, Rb2, (float*)d_out);
}

// round 2
// speedup vs baseline: 2.6311x; 2.6311x over previous
#include <cuda_runtime.h>
#include <cuda_fp16.h>
#include <cstdint>

// GraphSAGE-style net, N=100000, K=32 neighbors, D=64, fused single pass.
// Math identity: stage-2 max over {self=node0, neighbors=nodes 1..} of
// relu(embs_1 @ aggr2_W^T + b) == elementwise max over ALL nodes. So:
//   per node: z=max_k(v_k.W1) ; a=relu(z+b1) ; e=l2norm(relu(a@WE^T)) ;
//             y=relu(e@W2^T+b2) ; fold y into global 64-wide max.
//   tail: tiny MLP on the 64-vector.
// Tensorized: warp handles 16 nodes; mma.sync m16n8k16 fp16 with 2-term
// split (3 products) => fp32-quality precision on tensor pipes.

#define NW 8
#define TPB 256
#define GRID 148

__device__ unsigned g_ymax[64];

// dynamic smem byte offsets
#define W1H 0
#define W1L 9216
#define WEH 18432
#define WEL 27648
#define W2H 36864
#define W2L 46080
#define B1O 55296
#define B2O 55552
#define ABUF 55808
#define AWSZ 4608              // per-warp A staging: hi 2304B + lo 2304B
#define SMEM_BYTES (ABUF + NW*AWSZ)

__global__ void init_ymax(){
    if (threadIdx.x < 64) g_ymax[threadIdx.x] = 0u;  // y >= 0 (relu)
}

__device__ __forceinline__ void mma16816(float* d, const unsigned* a, unsigned b0, unsigned b1){
    asm volatile("mma.sync.aligned.m16n8k16.row.col.f32.f16.f16.f32 "
        "{%0,%1,%2,%3}, {%4,%5,%6,%7}, {%8,%9}, {%0,%1,%2,%3};"
        : "+f"(d[0]), "+f"(d[1]), "+f"(d[2]), "+f"(d[3])
        : "r"(a[0]), "r"(a[1]), "r"(a[2]), "r"(a[3]), "r"(b0), "r"(b1));
}

// split a float pair into fp16 hi and fp16 lo (residual)
__device__ __forceinline__ void split2(float x, float y, unsigned &h, unsigned &l){
    __half2 h2 = __floats2half2_rn(x, y);
    float2 f  = __half22float2(h2);
    __half2 l2 = __floats2half2_rn(x - f.x, y - f.y);
    h = *(unsigned*)&h2;
    l = *(unsigned*)&l2;
}

__global__ __launch_bounds__(TPB, 1)
void sage_main(const float* __restrict__ xs, const float* __restrict__ xn,
               const float* __restrict__ W1, const float* __restrict__ b1,
               const float* __restrict__ WE,
               const float* __restrict__ W2a, const float* __restrict__ b2a,
               int nN)
{
    extern __shared__ char sm[];
    int tid = threadIdx.x;

    // ---- prep: weights -> fp16 hi/lo in smem, rows padded to 72 halfs ----
    for (int idx = tid; idx < 4096; idx += TPB){
        int d = idx >> 6, k = idx & 63;
        int o = d*72 + k;
        float x; __half h;
        x = W1[idx];  h = __float2half_rn(x);
        ((__half*)(sm+W1H))[o] = h;  ((__half*)(sm+W1L))[o] = __float2half_rn(x - __half2float(h));
        x = WE[idx];  h = __float2half_rn(x);
        ((__half*)(sm+WEH))[o] = h;  ((__half*)(sm+WEL))[o] = __float2half_rn(x - __half2float(h));
        x = W2a[idx]; h = __float2half_rn(x);
        ((__half*)(sm+W2H))[o] = h;  ((__half*)(sm+W2L))[o] = __float2half_rn(x - __half2float(h));
    }
    if (tid < 64){
        ((float*)(sm+B1O))[tid] = b1[tid];
        ((float*)(sm+B2O))[tid] = b2a[tid];
    }
    __syncthreads();

    int lane = tid & 31, wid = tid >> 5;
    int tig = lane & 3, grp = lane >> 2;        // mma quad layout
    int r = lane >> 1, p = lane & 1;            // staging: row, half-row part

    char* ah = sm + ABUF + wid*AWSZ;            // per-warp A hi halfs
    char* al = ah + 2304;                       // per-warp A lo halfs

    int gw = blockIdx.x*NW + wid;
    int gstride = GRID*NW;
    int ngroups = (nN + 15) >> 4;

    float gym[8][2];
    #pragma unroll
    for (int nt = 0; nt < 8; nt++){ gym[nt][0] = 0.f; gym[nt][1] = 0.f; }

    for (int g = gw; g < ngroups; g += gstride){
        int node = g*16 + r;
        if (node >= nN) node = nN - 1;           // duplicates are harmless under max
        const float4* selfp = (const float4*)(xs + (size_t)node*64) + p*8;
        const float4* nbp   = (const float4*)(xn + (size_t)node*2048) + p*8;

        float4 cur[8];
        #pragma unroll
        for (int q = 0; q < 8; q++) cur[q] = selfp[q];

        float M[8][4];
        #pragma unroll
        for (int nt = 0; nt < 8; nt++)
            #pragma unroll
            for (int i = 0; i < 4; i++) M[nt][i] = -3.402823466e38f;

        #pragma unroll 1
        for (int j = 0; j < 33; j++){
            // convert cur -> fp16 hi/lo, store to per-warp smem tile
            #pragma unroll
            for (int q = 0; q < 8; q++){
                float4 v = cur[q];
                unsigned h0,l0,h1,l1;
                split2(v.x, v.y, h0, l0);
                split2(v.z, v.w, h1, l1);
                int ob = r*144 + p*64 + q*8;     // bytes
                *(uint2*)(ah + ob) = make_uint2(h0, h1);
                *(uint2*)(al + ob) = make_uint2(l0, l1);
            }
            __syncwarp();

            // prefetch next j while mma runs
            float4 nxt[8];
            if (j < 32){
                const float4* sp = nbp + j*16;
                #pragma unroll
                for (int q = 0; q < 8; q++) nxt[q] = sp[q];
            }

            // A fragments for all 4 k-tiles (hi and lo)
            unsigned Afh[4][4], Afl[4][4];
            #pragma unroll
            for (int kt = 0; kt < 4; kt++){
                int ob = kt*32 + tig*4;          // bytes within row
                Afh[kt][0] = *(unsigned*)(ah + grp*144     + ob);
                Afh[kt][1] = *(unsigned*)(ah + (grp+8)*144 + ob);
                Afh[kt][2] = *(unsigned*)(ah + grp*144     + ob + 16);
                Afh[kt][3] = *(unsigned*)(ah + (grp+8)*144 + ob + 16);
                Afl[kt][0] = *(unsigned*)(al + grp*144     + ob);
                Afl[kt][1] = *(unsigned*)(al + (grp+8)*144 + ob);
                Afl[kt][2] = *(unsigned*)(al + grp*144     + ob + 16);
                Afl[kt][3] = *(unsigned*)(al + (grp+8)*144 + ob + 16);
            }
            __syncwarp();                        // frags read; next STS may proceed

            float D[8][4];
            #pragma unroll
            for (int nt = 0; nt < 8; nt++)
                #pragma unroll
                for (int i = 0; i < 4; i++) D[nt][i] = 0.f;

            #pragma unroll
            for (int nt = 0; nt < 8; nt++){
                int nrow = (nt*8 + grp)*144;
                #pragma unroll
                for (int kt = 0; kt < 4; kt++){
                    int ob = nrow + kt*32 + tig*4;
                    unsigned bh0 = *(unsigned*)(sm + W1H + ob);
                    unsigned bh1 = *(unsigned*)(sm + W1H + ob + 16);
                    unsigned bl0 = *(unsigned*)(sm + W1L + ob);
                    unsigned bl1 = *(unsigned*)(sm + W1L + ob + 16);
                    mma16816(D[nt], Afh[kt], bh0, bh1);
                    mma16816(D[nt], Afh[kt], bl0, bl1);
                    mma16816(D[nt], Afl[kt], bh0, bh1);
                }
            }
            #pragma unroll
            for (int nt = 0; nt < 8; nt++)
                #pragma unroll
                for (int i = 0; i < 4; i++) M[nt][i] = fmaxf(M[nt][i], D[nt][i]);

            #pragma unroll
            for (int q = 0; q < 8; q++) cur[q] = nxt[q];
        }

        // ---- a = relu(z + b1); cols of frag = nt*8 + 2*tig + {0,1} ----
        float av[8][4];
        #pragma unroll
        for (int nt = 0; nt < 8; nt++){
            float2 bb = *(const float2*)(sm + B1O + (nt*8 + 2*tig)*4);
            av[nt][0] = fmaxf(M[nt][0] + bb.x, 0.f);
            av[nt][1] = fmaxf(M[nt][1] + bb.y, 0.f);
            av[nt][2] = fmaxf(M[nt][2] + bb.x, 0.f);
            av[nt][3] = fmaxf(M[nt][3] + bb.y, 0.f);
        }

        // ---- phase B: E = a @ WE^T (frag-chained A, 3-term) ----
        unsigned Fh[4][4], Fl[4][4];
        #pragma unroll
        for (int kt = 0; kt < 4; kt++){
            split2(av[2*kt][0],   av[2*kt][1],   Fh[kt][0], Fl[kt][0]);
            split2(av[2*kt][2],   av[2*kt][3],   Fh[kt][1], Fl[kt][1]);
            split2(av[2*kt+1][0], av[2*kt+1][1], Fh[kt][2], Fl[kt][2]);
            split2(av[2*kt+1][2], av[2*kt+1][3], Fh[kt][3], Fl[kt][3]);
        }
        float E[8][4];
        #pragma unroll
        for (int nt = 0; nt < 8; nt++){
            #pragma unroll
            for (int i = 0; i < 4; i++) E[nt][i] = 0.f;
            int nrow = (nt*8 + grp)*144;
            #pragma unroll
            for (int kt = 0; kt < 4; kt++){
                int ob = nrow + kt*32 + tig*4;
                unsigned bh0 = *(unsigned*)(sm + WEH + ob);
                unsigned bh1 = *(unsigned*)(sm + WEH + ob + 16);
                unsigned bl0 = *(unsigned*)(sm + WEL + ob);
                unsigned bl1 = *(unsigned*)(sm + WEL + ob + 16);
                mma16816(E[nt], Fh[kt], bh0, bh1);
                mma16816(E[nt], Fh[kt], bl0, bl1);
                mma16816(E[nt], Fl[kt], bh0, bh1);
            }
            #pragma unroll
            for (int i = 0; i < 4; i++) E[nt][i] = fmaxf(E[nt][i], 0.f);
        }

        // ---- l2 normalize rows (row grp via c0,c1; row grp+8 via c2,c3) ----
        float s0 = 0.f, s1 = 0.f;
        #pragma unroll
        for (int nt = 0; nt < 8; nt++){
            s0 += E[nt][0]*E[nt][0] + E[nt][1]*E[nt][1];
            s1 += E[nt][2]*E[nt][2] + E[nt][3]*E[nt][3];
        }
        s0 += __shfl_xor_sync(0xffffffffu, s0, 1);
        s0 += __shfl_xor_sync(0xffffffffu, s0, 2);
        s1 += __shfl_xor_sync(0xffffffffu, s1, 1);
        s1 += __shfl_xor_sync(0xffffffffu, s1, 2);
        float i0 = (s0 > 0.f) ? (1.f/sqrtf(s0)) : 0.f;
        float i1 = (s1 > 0.f) ? (1.f/sqrtf(s1)) : 0.f;
        #pragma unroll
        for (int nt = 0; nt < 8; nt++){
            E[nt][0] *= i0; E[nt][1] *= i0;
            E[nt][2] *= i1; E[nt][3] *= i1;
        }

        // ---- phase C: Y = en @ W2^T + b2, relu, fold node-max into gym ----
        #pragma unroll
        for (int kt = 0; kt < 4; kt++){
            split2(E[2*kt][0],   E[2*kt][1],   Fh[kt][0], Fl[kt][0]);
            split2(E[2*kt][2],   E[2*kt][3],   Fh[kt][1], Fl[kt][1]);
            split2(E[2*kt+1][0], E[2*kt+1][1], Fh[kt][2], Fl[kt][2]);
            split2(E[2*kt+1][2], E[2*kt+1][3], Fh[kt][3], Fl[kt][3]);
        }
        #pragma unroll
        for (int nt = 0; nt < 8; nt++){
            float Y[4];
            #pragma unroll
            for (int i = 0; i < 4; i++) Y[i] = 0.f;
            int nrow = (nt*8 + grp)*144;
            #pragma unroll
            for (int kt = 0; kt < 4; kt++){
                int ob = nrow + kt*32 + tig*4;
                unsigned bh0 = *(unsigned*)(sm + W2H + ob);
                unsigned bh1 = *(unsigned*)(sm + W2H + ob + 16);
                unsigned bl0 = *(unsigned*)(sm + W2L + ob);
                unsigned bl1 = *(unsigned*)(sm + W2L + ob + 16);
                mma16816(Y, Fh[kt], bh0, bh1);
                mma16816(Y, Fh[kt], bl0, bl1);
                mma16816(Y, Fl[kt], bh0, bh1);
            }
            float2 bb = *(const float2*)(sm + B2O + (nt*8 + 2*tig)*4);
            float y0 = fmaxf(Y[0] + bb.x, 0.f);
            float y1 = fmaxf(Y[1] + bb.y, 0.f);
            float y2 = fmaxf(Y[2] + bb.x, 0.f);
            float y3 = fmaxf(Y[3] + bb.y, 0.f);
            gym[nt][0] = fmaxf(gym[nt][0], fmaxf(y0, y2));
            gym[nt][1] = fmaxf(gym[nt][1], fmaxf(y1, y3));
        }
        __syncwarp();
    }

    // reduce gym across the 8 row-groups (lanes sharing tig), then atomics
    #pragma unroll
    for (int nt = 0; nt < 8; nt++){
        #pragma unroll
        for (int off = 4; off < 32; off <<= 1){
            gym[nt][0] = fmaxf(gym[nt][0], __shfl_xor_sync(0xffffffffu, gym[nt][0], off));
            gym[nt][1] = fmaxf(gym[nt][1], __shfl_xor_sync(0xffffffffu, gym[nt][1], off));
        }
    }
    if (grp == 0){
        #pragma unroll
        for (int nt = 0; nt < 8; nt++){
            atomicMax(&g_ymax[nt*8 + 2*tig],     __float_as_uint(gym[nt][0]));
            atomicMax(&g_ymax[nt*8 + 2*tig + 1], __float_as_uint(gym[nt][1]));
        }
    }
}

__global__ void sage_final(const float* __restrict__ E2, const float* __restrict__ RW1,
                           const float* __restrict__ Rb1, const float* __restrict__ RW2,
                           const float* __restrict__ Rb2, float* __restrict__ out)
{
    __shared__ float a2[64], t2[64], hs[64];
    __shared__ float sinv;
    int d = threadIdx.x;
    a2[d] = __uint_as_float(g_ymax[d]);
    __syncthreads();
    float s = 0.f;
    #pragma unroll
    for (int i = 0; i < 64; i++) s += a2[i]*E2[d*64 + i];
    s = fmaxf(s, 0.f);
    t2[d] = s;
    __syncthreads();
    if (d == 0){
        float acc = 0.f;
        for (int i = 0; i < 64; i++) acc += t2[i]*t2[i];
        float nr = sqrtf(acc);
        sinv = (nr > 0.f) ? (1.f/nr) : 0.f;
    }
    __syncthreads();
    a2[d] = t2[d]*sinv;
    __syncthreads();
    float h = Rb1[d];
    #pragma unroll
    for (int i = 0; i < 64; i++) h += a2[i]*RW1[d*64 + i];
    h = fmaxf(h, 0.f);
    hs[d] = h;
    __syncthreads();
    if (d == 0){
        float o = Rb2[0];
        for (int i = 0; i < 64; i++) o += hs[i]*RW2[i];
        out[0] = o;
    }
}

extern "C" void kernel_launch(void* const* d_in, const int* in_sizes, int n_in,
                              void* d_out, int out_size)
{
    const float* xs  = (const float*)d_in[0];
    const float* xn  = (const float*)d_in[1];
    const float* W1  = (const float*)d_in[2];
    const float* b1  = (const float*)d_in[3];
    const float* WE  = (const float*)d_in[4];
    const float* W2a = (const float*)d_in[5];
    const float* b2a = (const float*)d_in[6];
    const float* E2  = (const float*)d_in[7];
    const float* RW1 = (const float*)d_in[8];
    const float* Rb1 = (const float*)d_in[9];
    const float* RW2 = (const float*)d_in[10];
    const float* Rb2 = (const float*)d_in[11];
    int nN = in_sizes[0] / 64;

    cudaFuncSetAttribute(sage_main, cudaFuncAttributeMaxDynamicSharedMemorySize, SMEM_BYTES);
    init_ymax<<<1, 64>>>();
    sage_main<<<GRID, TPB, SMEM_BYTES>>>(xs, xn, W1, b1, WE, W2a, b2a, nN);
    sage_final<<<1, 64>>>(E2, RW1, Rb1, RW2, Rb2, (float*)d_out);
}

// round 3
// speedup vs baseline: 2.7725x; 1.0537x over previous
#include <cuda_runtime.h>
#include <cuda_fp16.h>
#include <cstdint>

// GraphSAGE-style net, N=100000, K=32 neighbors, D=64, fused single pass.
// Identity: stage-2 max over {self, neighbors} of relu(embs_1 @ W2^T + b)
// == elementwise max over ALL nodes' y. So one fused pass:
//   per node: z=max_k(v_k.W1) ; a=relu(z+b1) ; e=l2norm(relu(a@WE^T)) ;
//             y=relu(e@W2^T+b2) ; fold into global 64-wide max; tiny tail MLP.
// Tensorized: warp owns 16 nodes; mma.sync m16n8k16 fp16 2-term split
// (3 products) => ~fp32 precision. R3: 16 warps/SM + tight registers for
// memory-latency hiding.

#define NW 16
#define TPB 512
#define GRID 148

__device__ unsigned g_ymax[64];

// dynamic smem byte offsets
#define W1H 0
#define W1L 9216
#define WEH 18432
#define WEL 27648
#define W2H 36864
#define W2L 46080
#define B1O 55296
#define B2O 55552
#define ABUF 55808
#define AWSZ 4608              // per-warp A staging: hi 2304B + lo 2304B
#define SMEM_BYTES (ABUF + NW*AWSZ)

__global__ void init_ymax(){
    if (threadIdx.x < 64) g_ymax[threadIdx.x] = 0u;  // y >= 0 (relu)
}

__device__ __forceinline__ void mma16816(float* d, const unsigned* a, unsigned b0, unsigned b1){
    asm volatile("mma.sync.aligned.m16n8k16.row.col.f32.f16.f16.f32 "
        "{%0,%1,%2,%3}, {%4,%5,%6,%7}, {%8,%9}, {%0,%1,%2,%3};"
        : "+f"(d[0]), "+f"(d[1]), "+f"(d[2]), "+f"(d[3])
        : "r"(a[0]), "r"(a[1]), "r"(a[2]), "r"(a[3]), "r"(b0), "r"(b1));
}

// split a float pair into fp16 hi and fp16 lo (residual)
__device__ __forceinline__ void split2(float x, float y, unsigned &h, unsigned &l){
    __half2 h2 = __floats2half2_rn(x, y);
    float2 f  = __half22float2(h2);
    __half2 l2 = __floats2half2_rn(x - f.x, y - f.y);
    h = *(unsigned*)&h2;
    l = *(unsigned*)&l2;
}

__global__ __launch_bounds__(TPB, 1)
void sage_main(const float* __restrict__ xs, const float* __restrict__ xn,
               const float* __restrict__ W1, const float* __restrict__ b1,
               const float* __restrict__ WE,
               const float* __restrict__ W2a, const float* __restrict__ b2a,
               int nN)
{
    extern __shared__ char sm[];
    int tid = threadIdx.x;

    // ---- prep: weights -> fp16 hi/lo in smem, rows padded to 72 halfs ----
    for (int idx = tid; idx < 4096; idx += TPB){
        int d = idx >> 6, k = idx & 63;
        int o = d*72 + k;
        float x; __half h;
        x = W1[idx];  h = __float2half_rn(x);
        ((__half*)(sm+W1H))[o] = h;  ((__half*)(sm+W1L))[o] = __float2half_rn(x - __half2float(h));
        x = WE[idx];  h = __float2half_rn(x);
        ((__half*)(sm+WEH))[o] = h;  ((__half*)(sm+WEL))[o] = __float2half_rn(x - __half2float(h));
        x = W2a[idx]; h = __float2half_rn(x);
        ((__half*)(sm+W2H))[o] = h;  ((__half*)(sm+W2L))[o] = __float2half_rn(x - __half2float(h));
    }
    if (tid < 64){
        ((float*)(sm+B1O))[tid] = b1[tid];
        ((float*)(sm+B2O))[tid] = b2a[tid];
    }
    __syncthreads();

    int lane = tid & 31, wid = tid >> 5;
    int tig = lane & 3, grp = lane >> 2;        // mma quad layout
    int r = lane >> 1, p = lane & 1;            // staging: row, half-row part

    char* ah = sm + ABUF + wid*AWSZ;            // per-warp A hi halfs (row stride 144B)
    char* al = ah + 2304;                       // per-warp A lo halfs

    int gw = blockIdx.x*NW + wid;
    int gstride = GRID*NW;
    int ngroups = (nN + 15) >> 4;

    float gym[8][2];
    #pragma unroll
    for (int nt = 0; nt < 8; nt++){ gym[nt][0] = 0.f; gym[nt][1] = 0.f; }

    for (int g = gw; g < ngroups; g += gstride){
        int node = g*16 + r;
        if (node >= nN) node = nN - 1;           // duplicates harmless under max
        const float4* selfp = (const float4*)(xs + (size_t)node*64) + p*8;
        const float4* nbp   = (const float4*)(xn + (size_t)node*2048) + p*8;

        float4 cur[8];
        #pragma unroll
        for (int q = 0; q < 8; q++) cur[q] = selfp[q];

        float M[8][4];
        #pragma unroll
        for (int nt = 0; nt < 8; nt++)
            #pragma unroll
            for (int i = 0; i < 4; i++) M[nt][i] = -3.402823466e38f;

        #pragma unroll 1
        for (int j = 0; j < 33; j++){
            // convert cur -> fp16 hi/lo, store to per-warp smem tile; cur dies here
            #pragma unroll
            for (int q = 0; q < 8; q++){
                float4 v = cur[q];
                unsigned h0,l0,h1,l1;
                split2(v.x, v.y, h0, l0);
                split2(v.z, v.w, h1, l1);
                int ob = r*144 + p*64 + q*8;     // bytes
                *(uint2*)(ah + ob) = make_uint2(h0, h1);
                *(uint2*)(al + ob) = make_uint2(l0, l1);
            }
            __syncwarp();

            // prefetch next j into the SAME registers (in flight across the MMAs)
            if (j < 32){
                const float4* sp = nbp + j*16;
                #pragma unroll
                for (int q = 0; q < 8; q++) cur[q] = sp[q];
            }

            // A fragments for all 4 k-tiles (hi and lo); row stride 144B is
            // conflict-free for this lane->addr map
            unsigned Afh[4][4], Afl[4][4];
            #pragma unroll
            for (int kt = 0; kt < 4; kt++){
                int ob = kt*32 + tig*4;          // bytes within row
                Afh[kt][0] = *(unsigned*)(ah + grp*144     + ob);
                Afh[kt][1] = *(unsigned*)(ah + (grp+8)*144 + ob);
                Afh[kt][2] = *(unsigned*)(ah + grp*144     + ob + 16);
                Afh[kt][3] = *(unsigned*)(ah + (grp+8)*144 + ob + 16);
                Afl[kt][0] = *(unsigned*)(al + grp*144     + ob);
                Afl[kt][1] = *(unsigned*)(al + (grp+8)*144 + ob);
                Afl[kt][2] = *(unsigned*)(al + grp*144     + ob + 16);
                Afl[kt][3] = *(unsigned*)(al + (grp+8)*144 + ob + 16);
            }
            __syncwarp();                        // frags read; next STS may proceed

            #pragma unroll
            for (int nt = 0; nt < 8; nt++){
                float D[4] = {0.f, 0.f, 0.f, 0.f};
                int nrow = (nt*8 + grp)*144;
                #pragma unroll
                for (int kt = 0; kt < 4; kt++){
                    int ob = nrow + kt*32 + tig*4;
                    unsigned bh0 = *(unsigned*)(sm + W1H + ob);
                    unsigned bh1 = *(unsigned*)(sm + W1H + ob + 16);
                    unsigned bl0 = *(unsigned*)(sm + W1L + ob);
                    unsigned bl1 = *(unsigned*)(sm + W1L + ob + 16);
                    mma16816(D, Afh[kt], bh0, bh1);
                    mma16816(D, Afh[kt], bl0, bl1);
                    mma16816(D, Afl[kt], bh0, bh1);
                }
                M[nt][0] = fmaxf(M[nt][0], D[0]);
                M[nt][1] = fmaxf(M[nt][1], D[1]);
                M[nt][2] = fmaxf(M[nt][2], D[2]);
                M[nt][3] = fmaxf(M[nt][3], D[3]);
            }
        }

        // ---- a = relu(z + b1); cols of frag = nt*8 + 2*tig + {0,1} ----
        float av[8][4];
        #pragma unroll
        for (int nt = 0; nt < 8; nt++){
            float2 bb = *(const float2*)(sm + B1O + (nt*8 + 2*tig)*4);
            av[nt][0] = fmaxf(M[nt][0] + bb.x, 0.f);
            av[nt][1] = fmaxf(M[nt][1] + bb.y, 0.f);
            av[nt][2] = fmaxf(M[nt][2] + bb.x, 0.f);
            av[nt][3] = fmaxf(M[nt][3] + bb.y, 0.f);
        }

        // ---- phase B: E = a @ WE^T (frag-chained A, 3-term) ----
        unsigned Fh[4][4], Fl[4][4];
        #pragma unroll
        for (int kt = 0; kt < 4; kt++){
            split2(av[2*kt][0],   av[2*kt][1],   Fh[kt][0], Fl[kt][0]);
            split2(av[2*kt][2],   av[2*kt][3],   Fh[kt][1], Fl[kt][1]);
            split2(av[2*kt+1][0], av[2*kt+1][1], Fh[kt][2], Fl[kt][2]);
            split2(av[2*kt+1][2], av[2*kt+1][3], Fh[kt][3], Fl[kt][3]);
        }
        float E[8][4];
        #pragma unroll
        for (int nt = 0; nt < 8; nt++){
            #pragma unroll
            for (int i = 0; i < 4; i++) E[nt][i] = 0.f;
            int nrow = (nt*8 + grp)*144;
            #pragma unroll
            for (int kt = 0; kt < 4; kt++){
                int ob = nrow + kt*32 + tig*4;
                unsigned bh0 = *(unsigned*)(sm + WEH + ob);
                unsigned bh1 = *(unsigned*)(sm + WEH + ob + 16);
                unsigned bl0 = *(unsigned*)(sm + WEL + ob);
                unsigned bl1 = *(unsigned*)(sm + WEL + ob + 16);
                mma16816(E[nt], Fh[kt], bh0, bh1);
                mma16816(E[nt], Fh[kt], bl0, bl1);
                mma16816(E[nt], Fl[kt], bh0, bh1);
            }
            #pragma unroll
            for (int i = 0; i < 4; i++) E[nt][i] = fmaxf(E[nt][i], 0.f);
        }

        // ---- l2 normalize rows (row grp via c0,c1; row grp+8 via c2,c3) ----
        float s0 = 0.f, s1 = 0.f;
        #pragma unroll
        for (int nt = 0; nt < 8; nt++){
            s0 += E[nt][0]*E[nt][0] + E[nt][1]*E[nt][1];
            s1 += E[nt][2]*E[nt][2] + E[nt][3]*E[nt][3];
        }
        s0 += __shfl_xor_sync(0xffffffffu, s0, 1);
        s0 += __shfl_xor_sync(0xffffffffu, s0, 2);
        s1 += __shfl_xor_sync(0xffffffffu, s1, 1);
        s1 += __shfl_xor_sync(0xffffffffu, s1, 2);
        float i0 = (s0 > 0.f) ? (1.f/sqrtf(s0)) : 0.f;
        float i1 = (s1 > 0.f) ? (1.f/sqrtf(s1)) : 0.f;
        #pragma unroll
        for (int nt = 0; nt < 8; nt++){
            E[nt][0] *= i0; E[nt][1] *= i0;
            E[nt][2] *= i1; E[nt][3] *= i1;
        }

        // ---- phase C: Y = en @ W2^T + b2, relu, fold node-max into gym ----
        #pragma unroll
        for (int kt = 0; kt < 4; kt++){
            split2(E[2*kt][0],   E[2*kt][1],   Fh[kt][0], Fl[kt][0]);
            split2(E[2*kt][2],   E[2*kt][3],   Fh[kt][1], Fl[kt][1]);
            split2(E[2*kt+1][0], E[2*kt+1][1], Fh[kt][2], Fl[kt][2]);
            split2(E[2*kt+1][2], E[2*kt+1][3], Fh[kt][3], Fl[kt][3]);
        }
        #pragma unroll
        for (int nt = 0; nt < 8; nt++){
            float Y[4] = {0.f, 0.f, 0.f, 0.f};
            int nrow = (nt*8 + grp)*144;
            #pragma unroll
            for (int kt = 0; kt < 4; kt++){
                int ob = nrow + kt*32 + tig*4;
                unsigned bh0 = *(unsigned*)(sm + W2H + ob);
                unsigned bh1 = *(unsigned*)(sm + W2H + ob + 16);
                unsigned bl0 = *(unsigned*)(sm + W2L + ob);
                unsigned bl1 = *(unsigned*)(sm + W2L + ob + 16);
                mma16816(Y, Fh[kt], bh0, bh1);
                mma16816(Y, Fh[kt], bl0, bl1);
                mma16816(Y, Fl[kt], bh0, bh1);
            }
            float2 bb = *(const float2*)(sm + B2O + (nt*8 + 2*tig)*4);
            float y0 = fmaxf(Y[0] + bb.x, 0.f);
            float y1 = fmaxf(Y[1] + bb.y, 0.f);
            float y2 = fmaxf(Y[2] + bb.x, 0.f);
            float y3 = fmaxf(Y[3] + bb.y, 0.f);
            gym[nt][0] = fmaxf(gym[nt][0], fmaxf(y0, y2));
            gym[nt][1] = fmaxf(gym[nt][1], fmaxf(y1, y3));
        }
        __syncwarp();
    }

    // reduce gym across the 8 row-groups (lanes sharing tig), then atomics
    #pragma unroll
    for (int nt = 0; nt < 8; nt++){
        #pragma unroll
        for (int off = 4; off < 32; off <<= 1){
            gym[nt][0] = fmaxf(gym[nt][0], __shfl_xor_sync(0xffffffffu, gym[nt][0], off));
            gym[nt][1] = fmaxf(gym[nt][1], __shfl_xor_sync(0xffffffffu, gym[nt][1], off));
        }
    }
    if (grp == 0){
        #pragma unroll
        for (int nt = 0; nt < 8; nt++){
            atomicMax(&g_ymax[nt*8 + 2*tig],     __float_as_uint(gym[nt][0]));
            atomicMax(&g_ymax[nt*8 + 2*tig + 1], __float_as_uint(gym[nt][1]));
        }
    }
}

__global__ void sage_final(const float* __restrict__ E2, const float* __restrict__ RW1,
                           const float* __restrict__ Rb1, const float* __restrict__ RW2,
                           const float* __restrict__ Rb2, float* __restrict__ out)
{
    __shared__ float a2[64], t2[64], hs[64];
    __shared__ float sinv;
    int d = threadIdx.x;
    a2[d] = __uint_as_float(g_ymax[d]);
    __syncthreads();
    float s = 0.f;
    #pragma unroll
    for (int i = 0; i < 64; i++) s += a2[i]*E2[d*64 + i];
    s = fmaxf(s, 0.f);
    t2[d] = s;
    __syncthreads();
    if (d == 0){
        float acc = 0.f;
        for (int i = 0; i < 64; i++) acc += t2[i]*t2[i];
        float nr = sqrtf(acc);
        sinv = (nr > 0.f) ? (1.f/nr) : 0.f;
    }
    __syncthreads();
    a2[d] = t2[d]*sinv;
    __syncthreads();
    float h = Rb1[d];
    #pragma unroll
    for (int i = 0; i < 64; i++) h += a2[i]*RW1[d*64 + i];
    h = fmaxf(h, 0.f);
    hs[d] = h;
    __syncthreads();
    if (d == 0){
        float o = Rb2[0];
        for (int i = 0; i < 64; i++) o += hs[i]*RW2[i];
        out[0] = o;
    }
}

extern "C" void kernel_launch(void* const* d_in, const int* in_sizes, int n_in,
                              void* d_out, int out_size)
{
    const float* xs  = (const float*)d_in[0];
    const float* xn  = (const float*)d_in[1];
    const float* W1  = (const float*)d_in[2];
    const float* b1  = (const float*)d_in[3];
    const float* WE  = (const float*)d_in[4];
    const float* W2a = (const float*)d_in[5];
    const float* b2a = (const float*)d_in[6];
    const float* E2  = (const float*)d_in[7];
    const float* RW1 = (const float*)d_in[8];
    const float* Rb1 = (const float*)d_in[9];
    const float* RW2 = (const float*)d_in[10];
    const float* Rb2 = (const float*)d_in[11];
    int nN = in_sizes[0] / 64;

    cudaFuncSetAttribute(sage_main, cudaFuncAttributeMaxDynamicSharedMemorySize, SMEM_BYTES);
    init_ymax<<<1, 64>>>();
    sage_main<<<GRID, TPB, SMEM_BYTES>>>(xs, xn, W1, b1, WE, W2a, b2a, nN);
    sage_final<<<1, 64>>>(E2, RW1, Rb1, RW2, Rb2, (float*)d_out);
}

// round 5
// speedup vs baseline: 3.3183x; 1.1969x over previous
#include <cuda_runtime.h>
#include <cuda_fp16.h>
#include <cstdint>

// GraphSAGE-style net, N=100000, K=32 neighbors, D=64, fused single pass.
// Identity: stage-2 max over {self, neighbors} of relu(embs_1 @ W2^T + b)
// == elementwise max over ALL nodes' y. So one fused pass:
//   per node: z=max_k(v_k.W1) ; a=relu(z+b1) ; e=l2norm(relu(a@WE^T)) ;
//             y=relu(e@W2^T+b2) ; fold into global 64-wide max; tiny tail MLP.
// mma.sync m16n8k16 fp16 split (tcgen05 unavailable via this toolchain:
// PTX target compute_103 rejects 'a'-gated instructions).
// R5: hot loop uses 2-product split (Ah*Wh + Al*Wh, W-lo dropped) =>
// 1/3 fewer HMMAs, half the weight-fragment LDS. Phases B/C stay 3-product.

#define NW 16
#define TPB 512
#define GRID 148

__device__ unsigned g_ymax[64];

// dynamic smem byte offsets
#define W1H 0
#define W1L 9216
#define WEH 18432
#define WEL 27648
#define W2H 36864
#define W2L 46080
#define B1O 55296
#define B2O 55552
#define ABUF 55808
#define AWSZ 4608              // per-warp A staging: hi 2304B + lo 2304B
#define SMEM_BYTES (ABUF + NW*AWSZ)

__global__ void init_ymax(){
    if (threadIdx.x < 64) g_ymax[threadIdx.x] = 0u;  // y >= 0 (relu)
}

__device__ __forceinline__ void mma16816(float* d, const unsigned* a, unsigned b0, unsigned b1){
    asm volatile("mma.sync.aligned.m16n8k16.row.col.f32.f16.f16.f32 "
        "{%0,%1,%2,%3}, {%4,%5,%6,%7}, {%8,%9}, {%0,%1,%2,%3};"
        : "+f"(d[0]), "+f"(d[1]), "+f"(d[2]), "+f"(d[3])
        : "r"(a[0]), "r"(a[1]), "r"(a[2]), "r"(a[3]), "r"(b0), "r"(b1));
}

// split a float pair into fp16 hi and fp16 lo (residual)
__device__ __forceinline__ void split2(float x, float y, unsigned &h, unsigned &l){
    __half2 h2 = __floats2half2_rn(x, y);
    float2 f  = __half22float2(h2);
    __half2 l2 = __floats2half2_rn(x - f.x, y - f.y);
    h = *(unsigned*)&h2;
    l = *(unsigned*)&l2;
}

__global__ __launch_bounds__(TPB, 1)
void sage_main(const float* __restrict__ xs, const float* __restrict__ xn,
               const float* __restrict__ W1, const float* __restrict__ b1,
               const float* __restrict__ WE,
               const float* __restrict__ W2a, const float* __restrict__ b2a,
               int nN)
{
    extern __shared__ char sm[];
    int tid = threadIdx.x;

    // ---- prep: weights -> fp16 hi/lo in smem, rows padded to 72 halfs ----
    for (int idx = tid; idx < 4096; idx += TPB){
        int d = idx >> 6, k = idx & 63;
        int o = d*72 + k;
        float x; __half h;
        x = W1[idx];  h = __float2half_rn(x);
        ((__half*)(sm+W1H))[o] = h;  ((__half*)(sm+W1L))[o] = __float2half_rn(x - __half2float(h));
        x = WE[idx];  h = __float2half_rn(x);
        ((__half*)(sm+WEH))[o] = h;  ((__half*)(sm+WEL))[o] = __float2half_rn(x - __half2float(h));
        x = W2a[idx]; h = __float2half_rn(x);
        ((__half*)(sm+W2H))[o] = h;  ((__half*)(sm+W2L))[o] = __float2half_rn(x - __half2float(h));
    }
    if (tid < 64){
        ((float*)(sm+B1O))[tid] = b1[tid];
        ((float*)(sm+B2O))[tid] = b2a[tid];
    }
    __syncthreads();

    int lane = tid & 31, wid = tid >> 5;
    int tig = lane & 3, grp = lane >> 2;        // mma quad layout
    int r = lane >> 1, p = lane & 1;            // staging: row, half-row part

    char* ah = sm + ABUF + wid*AWSZ;            // per-warp A hi halfs (row stride 144B)
    char* al = ah + 2304;                       // per-warp A lo halfs

    int gw = blockIdx.x*NW + wid;
    int gstride = GRID*NW;
    int ngroups = (nN + 15) >> 4;

    float gym[8][2];
    #pragma unroll
    for (int nt = 0; nt < 8; nt++){ gym[nt][0] = 0.f; gym[nt][1] = 0.f; }

    for (int g = gw; g < ngroups; g += gstride){
        int node = g*16 + r;
        if (node >= nN) node = nN - 1;           // duplicates harmless under max
        const float4* selfp = (const float4*)(xs + (size_t)node*64) + p*8;
        const float4* nbp   = (const float4*)(xn + (size_t)node*2048) + p*8;

        float4 cur[8];
        #pragma unroll
        for (int q = 0; q < 8; q++) cur[q] = selfp[q];

        float M[8][4];
        #pragma unroll
        for (int nt = 0; nt < 8; nt++)
            #pragma unroll
            for (int i = 0; i < 4; i++) M[nt][i] = -3.402823466e38f;

        #pragma unroll 1
        for (int j = 0; j < 33; j++){
            // convert cur -> fp16 hi/lo, store to per-warp smem tile; cur dies here
            #pragma unroll
            for (int q = 0; q < 8; q++){
                float4 v = cur[q];
                unsigned h0,l0,h1,l1;
                split2(v.x, v.y, h0, l0);
                split2(v.z, v.w, h1, l1);
                int ob = r*144 + p*64 + q*8;     // bytes
                *(uint2*)(ah + ob) = make_uint2(h0, h1);
                *(uint2*)(al + ob) = make_uint2(l0, l1);
            }
            __syncwarp();

            // prefetch next j into the SAME registers (in flight across the MMAs)
            if (j < 32){
                const float4* sp = nbp + j*16;
                #pragma unroll
                for (int q = 0; q < 8; q++) cur[q] = sp[q];
            }

            // A fragments for all 4 k-tiles (hi and lo)
            unsigned Afh[4][4], Afl[4][4];
            #pragma unroll
            for (int kt = 0; kt < 4; kt++){
                int ob = kt*32 + tig*4;          // bytes within row
                Afh[kt][0] = *(unsigned*)(ah + grp*144     + ob);
                Afh[kt][1] = *(unsigned*)(ah + (grp+8)*144 + ob);
                Afh[kt][2] = *(unsigned*)(ah + grp*144     + ob + 16);
                Afh[kt][3] = *(unsigned*)(ah + (grp+8)*144 + ob + 16);
                Afl[kt][0] = *(unsigned*)(al + grp*144     + ob);
                Afl[kt][1] = *(unsigned*)(al + (grp+8)*144 + ob);
                Afl[kt][2] = *(unsigned*)(al + grp*144     + ob + 16);
                Afl[kt][3] = *(unsigned*)(al + (grp+8)*144 + ob + 16);
            }
            __syncwarp();                        // frags read; next STS may proceed

            // 2-product split in the hot loop: D = Ah*Wh + Al*Wh
            // (W-lo term dropped: ~2^-12 relative error, W-lo never loaded)
            #pragma unroll
            for (int nt = 0; nt < 8; nt++){
                float D[4] = {0.f, 0.f, 0.f, 0.f};
                int nrow = (nt*8 + grp)*144;
                #pragma unroll
                for (int kt = 0; kt < 4; kt++){
                    int ob = nrow + kt*32 + tig*4;
                    unsigned bh0 = *(unsigned*)(sm + W1H + ob);
                    unsigned bh1 = *(unsigned*)(sm + W1H + ob + 16);
                    mma16816(D, Afh[kt], bh0, bh1);
                    mma16816(D, Afl[kt], bh0, bh1);
                }
                M[nt][0] = fmaxf(M[nt][0], D[0]);
                M[nt][1] = fmaxf(M[nt][1], D[1]);
                M[nt][2] = fmaxf(M[nt][2], D[2]);
                M[nt][3] = fmaxf(M[nt][3], D[3]);
            }
        }

        // ---- a = relu(z + b1); cols of frag = nt*8 + 2*tig + {0,1} ----
        float av[8][4];
        #pragma unroll
        for (int nt = 0; nt < 8; nt++){
            float2 bb = *(const float2*)(sm + B1O + (nt*8 + 2*tig)*4);
            av[nt][0] = fmaxf(M[nt][0] + bb.x, 0.f);
            av[nt][1] = fmaxf(M[nt][1] + bb.y, 0.f);
            av[nt][2] = fmaxf(M[nt][2] + bb.x, 0.f);
            av[nt][3] = fmaxf(M[nt][3] + bb.y, 0.f);
        }

        // ---- phase B: E = a @ WE^T (frag-chained A, 3-term) ----
        unsigned Fh[4][4], Fl[4][4];
        #pragma unroll
        for (int kt = 0; kt < 4; kt++){
            split2(av[2*kt][0],   av[2*kt][1],   Fh[kt][0], Fl[kt][0]);
            split2(av[2*kt][2],   av[2*kt][3],   Fh[kt][1], Fl[kt][1]);
            split2(av[2*kt+1][0], av[2*kt+1][1], Fh[kt][2], Fl[kt][2]);
            split2(av[2*kt+1][2], av[2*kt+1][3], Fh[kt][3], Fl[kt][3]);
        }
        float E[8][4];
        #pragma unroll
        for (int nt = 0; nt < 8; nt++){
            #pragma unroll
            for (int i = 0; i < 4; i++) E[nt][i] = 0.f;
            int nrow = (nt*8 + grp)*144;
            #pragma unroll
            for (int kt = 0; kt < 4; kt++){
                int ob = nrow + kt*32 + tig*4;
                unsigned bh0 = *(unsigned*)(sm + WEH + ob);
                unsigned bh1 = *(unsigned*)(sm + WEH + ob + 16);
                unsigned bl0 = *(unsigned*)(sm + WEL + ob);
                unsigned bl1 = *(unsigned*)(sm + WEL + ob + 16);
                mma16816(E[nt], Fh[kt], bh0, bh1);
                mma16816(E[nt], Fh[kt], bl0, bl1);
                mma16816(E[nt], Fl[kt], bh0, bh1);
            }
            #pragma unroll
            for (int i = 0; i < 4; i++) E[nt][i] = fmaxf(E[nt][i], 0.f);
        }

        // ---- l2 normalize rows (row grp via c0,c1; row grp+8 via c2,c3) ----
        float s0 = 0.f, s1 = 0.f;
        #pragma unroll
        for (int nt = 0; nt < 8; nt++){
            s0 += E[nt][0]*E[nt][0] + E[nt][1]*E[nt][1];
            s1 += E[nt][2]*E[nt][2] + E[nt][3]*E[nt][3];
        }
        s0 += __shfl_xor_sync(0xffffffffu, s0, 1);
        s0 += __shfl_xor_sync(0xffffffffu, s0, 2);
        s1 += __shfl_xor_sync(0xffffffffu, s1, 1);
        s1 += __shfl_xor_sync(0xffffffffu, s1, 2);
        float i0 = (s0 > 0.f) ? (1.f/sqrtf(s0)) : 0.f;
        float i1 = (s1 > 0.f) ? (1.f/sqrtf(s1)) : 0.f;
        #pragma unroll
        for (int nt = 0; nt < 8; nt++){
            E[nt][0] *= i0; E[nt][1] *= i0;
            E[nt][2] *= i1; E[nt][3] *= i1;
        }

        // ---- phase C: Y = en @ W2^T + b2, relu, fold node-max into gym ----
        #pragma unroll
        for (int kt = 0; kt < 4; kt++){
            split2(E[2*kt][0],   E[2*kt][1],   Fh[kt][0], Fl[kt][0]);
            split2(E[2*kt][2],   E[2*kt][3],   Fh[kt][1], Fl[kt][1]);
            split2(E[2*kt+1][0], E[2*kt+1][1], Fh[kt][2], Fl[kt][2]);
            split2(E[2*kt+1][2], E[2*kt+1][3], Fh[kt][3], Fl[kt][3]);
        }
        #pragma unroll
        for (int nt = 0; nt < 8; nt++){
            float Y[4] = {0.f, 0.f, 0.f, 0.f};
            int nrow = (nt*8 + grp)*144;
            #pragma unroll
            for (int kt = 0; kt < 4; kt++){
                int ob = nrow + kt*32 + tig*4;
                unsigned bh0 = *(unsigned*)(sm + W2H + ob);
                unsigned bh1 = *(unsigned*)(sm + W2H + ob + 16);
                unsigned bl0 = *(unsigned*)(sm + W2L + ob);
                unsigned bl1 = *(unsigned*)(sm + W2L + ob + 16);
                mma16816(Y, Fh[kt], bh0, bh1);
                mma16816(Y, Fh[kt], bl0, bl1);
                mma16816(Y, Fl[kt], bh0, bh1);
            }
            float2 bb = *(const float2*)(sm + B2O + (nt*8 + 2*tig)*4);
            float y0 = fmaxf(Y[0] + bb.x, 0.f);
            float y1 = fmaxf(Y[1] + bb.y, 0.f);
            float y2 = fmaxf(Y[2] + bb.x, 0.f);
            float y3 = fmaxf(Y[3] + bb.y, 0.f);
            gym[nt][0] = fmaxf(gym[nt][0], fmaxf(y0, y2));
            gym[nt][1] = fmaxf(gym[nt][1], fmaxf(y1, y3));
        }
        __syncwarp();
    }

    // reduce gym across the 8 row-groups (lanes sharing tig), then atomics
    #pragma unroll
    for (int nt = 0; nt < 8; nt++){
        #pragma unroll
        for (int off = 4; off < 32; off <<= 1){
            gym[nt][0] = fmaxf(gym[nt][0], __shfl_xor_sync(0xffffffffu, gym[nt][0], off));
            gym[nt][1] = fmaxf(gym[nt][1], __shfl_xor_sync(0xffffffffu, gym[nt][1], off));
        }
    }
    if (grp == 0){
        #pragma unroll
        for (int nt = 0; nt < 8; nt++){
            atomicMax(&g_ymax[nt*8 + 2*tig],     __float_as_uint(gym[nt][0]));
            atomicMax(&g_ymax[nt*8 + 2*tig + 1], __float_as_uint(gym[nt][1]));
        }
    }
}

__global__ void sage_final(const float* __restrict__ E2, const float* __restrict__ RW1,
                           const float* __restrict__ Rb1, const float* __restrict__ RW2,
                           const float* __restrict__ Rb2, float* __restrict__ out)
{
    __shared__ float a2[64], t2[64], hs[64];
    __shared__ float sinv;
    int d = threadIdx.x;
    a2[d] = __uint_as_float(g_ymax[d]);
    __syncthreads();
    float s = 0.f;
    #pragma unroll
    for (int i = 0; i < 64; i++) s += a2[i]*E2[d*64 + i];
    s = fmaxf(s, 0.f);
    t2[d] = s;
    __syncthreads();
    if (d == 0){
        float acc = 0.f;
        for (int i = 0; i < 64; i++) acc += t2[i]*t2[i];
        float nr = sqrtf(acc);
        sinv = (nr > 0.f) ? (1.f/nr) : 0.f;
    }
    __syncthreads();
    a2[d] = t2[d]*sinv;
    __syncthreads();
    float h = Rb1[d];
    #pragma unroll
    for (int i = 0; i < 64; i++) h += a2[i]*RW1[d*64 + i];
    h = fmaxf(h, 0.f);
    hs[d] = h;
    __syncthreads();
    if (d == 0){
        float o = Rb2[0];
        for (int i = 0; i < 64; i++) o += hs[i]*RW2[i];
        out[0] = o;
    }
}

extern "C" void kernel_launch(void* const* d_in, const int* in_sizes, int n_in,
                              void* d_out, int out_size)
{
    const float* xs  = (const float*)d_in[0];
    const float* xn  = (const float*)d_in[1];
    const float* W1  = (const float*)d_in[2];
    const float* b1  = (const float*)d_in[3];
    const float* WE  = (const float*)d_in[4];
    const float* W2a = (const float*)d_in[5];
    const float* b2a = (const float*)d_in[6];
    const float* E2  = (const float*)d_in[7];
    const float* RW1 = (const float*)d_in[8];
    const float* Rb1 = (const float*)d_in[9];
    const float* RW2 = (const float*)d_in[10];
    const float* Rb2 = (const float*)d_in[11];
    int nN = in_sizes[0] / 64;

    cudaFuncSetAttribute(sage_main, cudaFuncAttributeMaxDynamicSharedMemorySize, SMEM_BYTES);
    init_ymax<<<1, 64>>>();
    sage_main<<<GRID, TPB, SMEM_BYTES>>>(xs, xn, W1, b1, WE, W2a, b2a, nN);
    sage_final<<<1, 64>>>(E2, RW1, Rb1, RW2, Rb2, (float*)d_out);
}

// round 6
// speedup vs baseline: 3.9437x; 1.1885x over previous
#include <cuda_runtime.h>
#include <cuda_fp16.h>
#include <cstdint>

// GraphSAGE-style net, N=100000, K=32 neighbors, D=64, fused single pass.
// Identity: stage-2 max over {self, neighbors} == elementwise max over ALL
// nodes of y = relu(e @ W2^T + b2). Fused per node:
//   z=max_k(v_k.W1); a=relu(z+b1); e=l2norm(relu(a@WE^T)); y=relu(e@W2^T+b2);
//   global 64-wide max; tiny tail MLP.
// mma.sync m16n8k16 (tcgen05 not available: toolchain targets compute_103).
// R6: hot loop = single fp16 product (A-hi x W-hi); W1 repacked in SMEM in
// per-thread fragment order so weight frags load as 2x LDS.128 per nt.
// Phases B/C remain 3-product split for precision.

#define NW 16
#define TPB 512
#define GRID 148

__device__ unsigned g_ymax[64];

// dynamic smem byte offsets
#define W1P 0                 // W1 hi, fragment-packed, 64 rows x 144B
#define WEH 9216
#define WEL 18432
#define W2H 27648
#define W2L 36864
#define B1O 46080
#define B2O 46336
#define ABUF 46592
#define AWSZ 2304             // per-warp A staging (hi only): 16 rows x 144B
#define SMEM_BYTES (ABUF + NW*AWSZ)

__global__ void init_ymax(){
    if (threadIdx.x < 64) g_ymax[threadIdx.x] = 0u;  // y >= 0 (relu)
}

__device__ __forceinline__ void mma16816(float* d, const unsigned* a, unsigned b0, unsigned b1){
    asm volatile("mma.sync.aligned.m16n8k16.row.col.f32.f16.f16.f32 "
        "{%0,%1,%2,%3}, {%4,%5,%6,%7}, {%8,%9}, {%0,%1,%2,%3};"
        : "+f"(d[0]), "+f"(d[1]), "+f"(d[2]), "+f"(d[3])
        : "r"(a[0]), "r"(a[1]), "r"(a[2]), "r"(a[3]), "r"(b0), "r"(b1));
}

// split a float pair into fp16 hi and fp16 lo (residual) -- used in B/C phases
__device__ __forceinline__ void split2(float x, float y, unsigned &h, unsigned &l){
    __half2 h2 = __floats2half2_rn(x, y);
    float2 f  = __half22float2(h2);
    __half2 l2 = __floats2half2_rn(x - f.x, y - f.y);
    h = *(unsigned*)&h2;
    l = *(unsigned*)&l2;
}
__device__ __forceinline__ unsigned pack2(float x, float y){
    __half2 h2 = __floats2half2_rn(x, y);
    return *(unsigned*)&h2;
}

__global__ __launch_bounds__(TPB, 1)
void sage_main(const float* __restrict__ xs, const float* __restrict__ xn,
               const float* __restrict__ W1, const float* __restrict__ b1,
               const float* __restrict__ WE,
               const float* __restrict__ W2a, const float* __restrict__ b2a,
               int nN)
{
    extern __shared__ char sm[];
    int tid = threadIdx.x;

    // ---- prep weights ----
    // W1: hi-only, fragment-packed. Element (d,k) lives at
    //   d*144 + ((k&7)>>1)*32 + ((k>>5)&1)*16 + ((k>>4)&1)*8 + ((k>>3)&1)*4 + (k&1)*2
    // so per (d, tig) one LDS.128 yields {kt0 b0, kt0 b1, kt1 b0, kt1 b1}.
    for (int idx = tid; idx < 4096; idx += TPB){
        int d = idx >> 6, k = idx & 63;
        float x = W1[idx];
        int ob = d*144 + ((k&7)>>1)*32 + ((k>>5)&1)*16 + ((k>>4)&1)*8 + ((k>>3)&1)*4 + (k&1)*2;
        *(__half*)(sm + W1P + ob) = __float2half_rn(x);
        // WE / W2: hi+lo, plain 72-half rows (144B stride)
        int o = d*72 + k;
        __half h;
        x = WE[idx];  h = __float2half_rn(x);
        ((__half*)(sm+WEH))[o] = h;  ((__half*)(sm+WEL))[o] = __float2half_rn(x - __half2float(h));
        x = W2a[idx]; h = __float2half_rn(x);
        ((__half*)(sm+W2H))[o] = h;  ((__half*)(sm+W2L))[o] = __float2half_rn(x - __half2float(h));
    }
    if (tid < 64){
        ((float*)(sm+B1O))[tid] = b1[tid];
        ((float*)(sm+B2O))[tid] = b2a[tid];
    }
    __syncthreads();

    int lane = tid & 31, wid = tid >> 5;
    int tig = lane & 3, grp = lane >> 2;        // mma quad layout
    int r = lane >> 1, p = lane & 1;            // staging: row, half-row part

    char* ah = sm + ABUF + wid*AWSZ;            // per-warp A hi halfs (row stride 144B)

    int gw = blockIdx.x*NW + wid;
    int gstride = GRID*NW;
    int ngroups = (nN + 15) >> 4;

    float gym[8][2];
    #pragma unroll
    for (int nt = 0; nt < 8; nt++){ gym[nt][0] = 0.f; gym[nt][1] = 0.f; }

    for (int g = gw; g < ngroups; g += gstride){
        int node = g*16 + r;
        if (node >= nN) node = nN - 1;           // duplicates harmless under max
        const float4* selfp = (const float4*)(xs + (size_t)node*64) + p*8;
        const float4* nbp   = (const float4*)(xn + (size_t)node*2048) + p*8;

        float4 cur[8];
        #pragma unroll
        for (int q = 0; q < 8; q++) cur[q] = selfp[q];

        float M[8][4];
        #pragma unroll
        for (int nt = 0; nt < 8; nt++)
            #pragma unroll
            for (int i = 0; i < 4; i++) M[nt][i] = -3.402823466e38f;

        #pragma unroll 1
        for (int j = 0; j < 33; j++){
            // convert cur -> fp16 hi, store to per-warp tile: 4x STS.128
            #pragma unroll
            for (int i = 0; i < 4; i++){
                float4 v0 = cur[2*i], v1 = cur[2*i+1];
                unsigned h0 = pack2(v0.x, v0.y);
                unsigned h1 = pack2(v0.z, v0.w);
                unsigned h2 = pack2(v1.x, v1.y);
                unsigned h3 = pack2(v1.z, v1.w);
                *(uint4*)(ah + r*144 + p*64 + i*16) = make_uint4(h0,h1,h2,h3);
            }
            __syncwarp();

            // prefetch next j into the SAME registers
            if (j < 32){
                const float4* sp = nbp + j*16;
                #pragma unroll
                for (int q = 0; q < 8; q++) cur[q] = sp[q];
            }

            // A fragments (hi) for 4 k-tiles
            unsigned Af[4][4];
            #pragma unroll
            for (int kt = 0; kt < 4; kt++){
                int ob = kt*32 + tig*4;
                Af[kt][0] = *(unsigned*)(ah + grp*144     + ob);
                Af[kt][1] = *(unsigned*)(ah + (grp+8)*144 + ob);
                Af[kt][2] = *(unsigned*)(ah + grp*144     + ob + 16);
                Af[kt][3] = *(unsigned*)(ah + (grp+8)*144 + ob + 16);
            }
            __syncwarp();                        // frags read; next STS may proceed

            // single-product: D = Ah * Wh ; W frags via 2x LDS.128 per nt
            #pragma unroll
            for (int nt = 0; nt < 8; nt++){
                float D[4] = {0.f, 0.f, 0.f, 0.f};
                const char* wb = sm + W1P + (nt*8 + grp)*144 + tig*32;
                uint4 wa = *(const uint4*)(wb);
                uint4 wc = *(const uint4*)(wb + 16);
                mma16816(D, Af[0], wa.x, wa.y);
                mma16816(D, Af[1], wa.z, wa.w);
                mma16816(D, Af[2], wc.x, wc.y);
                mma16816(D, Af[3], wc.z, wc.w);
                M[nt][0] = fmaxf(M[nt][0], D[0]);
                M[nt][1] = fmaxf(M[nt][1], D[1]);
                M[nt][2] = fmaxf(M[nt][2], D[2]);
                M[nt][3] = fmaxf(M[nt][3], D[3]);
            }
        }

        // ---- a = relu(z + b1); cols of frag = nt*8 + 2*tig + {0,1} ----
        float av[8][4];
        #pragma unroll
        for (int nt = 0; nt < 8; nt++){
            float2 bb = *(const float2*)(sm + B1O + (nt*8 + 2*tig)*4);
            av[nt][0] = fmaxf(M[nt][0] + bb.x, 0.f);
            av[nt][1] = fmaxf(M[nt][1] + bb.y, 0.f);
            av[nt][2] = fmaxf(M[nt][2] + bb.x, 0.f);
            av[nt][3] = fmaxf(M[nt][3] + bb.y, 0.f);
        }

        // ---- phase B: E = a @ WE^T (frag-chained A, 3-term) ----
        unsigned Fh[4][4], Fl[4][4];
        #pragma unroll
        for (int kt = 0; kt < 4; kt++){
            split2(av[2*kt][0],   av[2*kt][1],   Fh[kt][0], Fl[kt][0]);
            split2(av[2*kt][2],   av[2*kt][3],   Fh[kt][1], Fl[kt][1]);
            split2(av[2*kt+1][0], av[2*kt+1][1], Fh[kt][2], Fl[kt][2]);
            split2(av[2*kt+1][2], av[2*kt+1][3], Fh[kt][3], Fl[kt][3]);
        }
        float E[8][4];
        #pragma unroll
        for (int nt = 0; nt < 8; nt++){
            #pragma unroll
            for (int i = 0; i < 4; i++) E[nt][i] = 0.f;
            int nrow = (nt*8 + grp)*144;
            #pragma unroll
            for (int kt = 0; kt < 4; kt++){
                int ob = nrow + kt*32 + tig*4;
                unsigned bh0 = *(unsigned*)(sm + WEH + ob);
                unsigned bh1 = *(unsigned*)(sm + WEH + ob + 16);
                unsigned bl0 = *(unsigned*)(sm + WEL + ob);
                unsigned bl1 = *(unsigned*)(sm + WEL + ob + 16);
                mma16816(E[nt], Fh[kt], bh0, bh1);
                mma16816(E[nt], Fh[kt], bl0, bl1);
                mma16816(E[nt], Fl[kt], bh0, bh1);
            }
            #pragma unroll
            for (int i = 0; i < 4; i++) E[nt][i] = fmaxf(E[nt][i], 0.f);
        }

        // ---- l2 normalize rows (row grp via c0,c1; row grp+8 via c2,c3) ----
        float s0 = 0.f, s1 = 0.f;
        #pragma unroll
        for (int nt = 0; nt < 8; nt++){
            s0 += E[nt][0]*E[nt][0] + E[nt][1]*E[nt][1];
            s1 += E[nt][2]*E[nt][2] + E[nt][3]*E[nt][3];
        }
        s0 += __shfl_xor_sync(0xffffffffu, s0, 1);
        s0 += __shfl_xor_sync(0xffffffffu, s0, 2);
        s1 += __shfl_xor_sync(0xffffffffu, s1, 1);
        s1 += __shfl_xor_sync(0xffffffffu, s1, 2);
        float i0 = (s0 > 0.f) ? (1.f/sqrtf(s0)) : 0.f;
        float i1 = (s1 > 0.f) ? (1.f/sqrtf(s1)) : 0.f;
        #pragma unroll
        for (int nt = 0; nt < 8; nt++){
            E[nt][0] *= i0; E[nt][1] *= i0;
            E[nt][2] *= i1; E[nt][3] *= i1;
        }

        // ---- phase C: Y = en @ W2^T + b2, relu, fold node-max into gym ----
        #pragma unroll
        for (int kt = 0; kt < 4; kt++){
            split2(E[2*kt][0],   E[2*kt][1],   Fh[kt][0], Fl[kt][0]);
            split2(E[2*kt][2],   E[2*kt][3],   Fh[kt][1], Fl[kt][1]);
            split2(E[2*kt+1][0], E[2*kt+1][1], Fh[kt][2], Fl[kt][2]);
            split2(E[2*kt+1][2], E[2*kt+1][3], Fh[kt][3], Fl[kt][3]);
        }
        #pragma unroll
        for (int nt = 0; nt < 8; nt++){
            float Y[4] = {0.f, 0.f, 0.f, 0.f};
            int nrow = (nt*8 + grp)*144;
            #pragma unroll
            for (int kt = 0; kt < 4; kt++){
                int ob = nrow + kt*32 + tig*4;
                unsigned bh0 = *(unsigned*)(sm + W2H + ob);
                unsigned bh1 = *(unsigned*)(sm + W2H + ob + 16);
                unsigned bl0 = *(unsigned*)(sm + W2L + ob);
                unsigned bl1 = *(unsigned*)(sm + W2L + ob + 16);
                mma16816(Y, Fh[kt], bh0, bh1);
                mma16816(Y, Fh[kt], bl0, bl1);
                mma16816(Y, Fl[kt], bh0, bh1);
            }
            float2 bb = *(const float2*)(sm + B2O + (nt*8 + 2*tig)*4);
            float y0 = fmaxf(Y[0] + bb.x, 0.f);
            float y1 = fmaxf(Y[1] + bb.y, 0.f);
            float y2 = fmaxf(Y[2] + bb.x, 0.f);
            float y3 = fmaxf(Y[3] + bb.y, 0.f);
            gym[nt][0] = fmaxf(gym[nt][0], fmaxf(y0, y2));
            gym[nt][1] = fmaxf(gym[nt][1], fmaxf(y1, y3));
        }
        __syncwarp();
    }

    // reduce gym across the 8 row-groups (lanes sharing tig), then atomics
    #pragma unroll
    for (int nt = 0; nt < 8; nt++){
        #pragma unroll
        for (int off = 4; off < 32; off <<= 1){
            gym[nt][0] = fmaxf(gym[nt][0], __shfl_xor_sync(0xffffffffu, gym[nt][0], off));
            gym[nt][1] = fmaxf(gym[nt][1], __shfl_xor_sync(0xffffffffu, gym[nt][1], off));
        }
    }
    if (grp == 0){
        #pragma unroll
        for (int nt = 0; nt < 8; nt++){
            atomicMax(&g_ymax[nt*8 + 2*tig],     __float_as_uint(gym[nt][0]));
            atomicMax(&g_ymax[nt*8 + 2*tig + 1], __float_as_uint(gym[nt][1]));
        }
    }
}

__global__ void sage_final(const float* __restrict__ E2, const float* __restrict__ RW1,
                           const float* __restrict__ Rb1, const float* __restrict__ RW2,
                           const float* __restrict__ Rb2, float* __restrict__ out)
{
    __shared__ float a2[64], t2[64], hs[64];
    __shared__ float sinv;
    int d = threadIdx.x;
    a2[d] = __uint_as_float(g_ymax[d]);
    __syncthreads();
    float s = 0.f;
    #pragma unroll
    for (int i = 0; i < 64; i++) s += a2[i]*E2[d*64 + i];
    s = fmaxf(s, 0.f);
    t2[d] = s;
    __syncthreads();
    if (d == 0){
        float acc = 0.f;
        for (int i = 0; i < 64; i++) acc += t2[i]*t2[i];
        float nr = sqrtf(acc);
        sinv = (nr > 0.f) ? (1.f/nr) : 0.f;
    }
    __syncthreads();
    a2[d] = t2[d]*sinv;
    __syncthreads();
    float h = Rb1[d];
    #pragma unroll
    for (int i = 0; i < 64; i++) h += a2[i]*RW1[d*64 + i];
    h = fmaxf(h, 0.f);
    hs[d] = h;
    __syncthreads();
    if (d == 0){
        float o = Rb2[0];
        for (int i = 0; i < 64; i++) o += hs[i]*RW2[i];
        out[0] = o;
    }
}

extern "C" void kernel_launch(void* const* d_in, const int* in_sizes, int n_in,
                              void* d_out, int out_size)
{
    const float* xs  = (const float*)d_in[0];
    const float* xn  = (const float*)d_in[1];
    const float* W1  = (const float*)d_in[2];
    const float* b1  = (const float*)d_in[3];
    const float* WE  = (const float*)d_in[4];
    const float* W2a = (const float*)d_in[5];
    const float* b2a = (const float*)d_in[6];
    const float* E2  = (const float*)d_in[7];
    const float* RW1 = (const float*)d_in[8];
    const float* Rb1 = (const float*)d_in[9];
    const float* RW2 = (const float*)d_in[10];
    const float* Rb2 = (const float*)d_in[11];
    int nN = in_sizes[0] / 64;

    cudaFuncSetAttribute(sage_main, cudaFuncAttributeMaxDynamicSharedMemorySize, SMEM_BYTES);
    init_ymax<<<1, 64>>>();
    sage_main<<<GRID, TPB, SMEM_BYTES>>>(xs, xn, W1, b1, WE, W2a, b2a, nN);
    sage_final<<<1, 64>>>(E2, RW1, Rb1, RW2, Rb2, (float*)d_out);
}

// round 7
// speedup vs baseline: 6.6109x; 1.6763x over previous
#include <cuda_runtime.h>
#include <cuda_fp16.h>
#include <cstdint>

// GraphSAGE-style net, N=100000, K=32 neighbors, D=64, fused single pass.
// Identity: stage-2 max over {self, neighbors} == elementwise max over ALL
// nodes of y = relu(e @ W2^T + b2). Fused per node:
//   z=max_k(v_k.W1); a=relu(z+b1); e=l2norm(relu(a@WE^T)); y=relu(e@W2^T+b2);
//   global 64-wide max; tiny tail MLP.
// R7: coalesced LDG (4 wavefronts/instr instead of 32) via lane remap,
// W1 B-fragments hoisted to registers (j-invariant), TPB=384.

#define NW 12
#define TPB 384
#define GRID 148

__device__ unsigned g_ymax[64];

// dynamic smem byte offsets
#define W1P 0                 // W1 hi, fragment-packed, 64 rows x 144B
#define WEH 9216
#define WEL 18432
#define W2H 27648
#define W2L 36864
#define B1O 46080
#define B2O 46336
#define ABUF 46592
#define AWSZ 2304             // per-warp A staging (hi only): 16 rows x 144B
#define SMEM_BYTES (ABUF + NW*AWSZ)

__global__ void init_ymax(){
    if (threadIdx.x < 64) g_ymax[threadIdx.x] = 0u;  // y >= 0 (relu)
}

__device__ __forceinline__ void mma16816(float* d, const unsigned* a, unsigned b0, unsigned b1){
    asm volatile("mma.sync.aligned.m16n8k16.row.col.f32.f16.f16.f32 "
        "{%0,%1,%2,%3}, {%4,%5,%6,%7}, {%8,%9}, {%0,%1,%2,%3};"
        : "+f"(d[0]), "+f"(d[1]), "+f"(d[2]), "+f"(d[3])
        : "r"(a[0]), "r"(a[1]), "r"(a[2]), "r"(a[3]), "r"(b0), "r"(b1));
}

__device__ __forceinline__ void split2(float x, float y, unsigned &h, unsigned &l){
    __half2 h2 = __floats2half2_rn(x, y);
    float2 f  = __half22float2(h2);
    __half2 l2 = __floats2half2_rn(x - f.x, y - f.y);
    h = *(unsigned*)&h2;
    l = *(unsigned*)&l2;
}
__device__ __forceinline__ unsigned pack2(float x, float y){
    __half2 h2 = __floats2half2_rn(x, y);
    return *(unsigned*)&h2;
}

__global__ __launch_bounds__(TPB, 1)
void sage_main(const float* __restrict__ xs, const float* __restrict__ xn,
               const float* __restrict__ W1, const float* __restrict__ b1,
               const float* __restrict__ WE,
               const float* __restrict__ W2a, const float* __restrict__ b2a,
               int nN)
{
    extern __shared__ char sm[];
    int tid = threadIdx.x;

    // ---- prep weights ----
    // W1: hi-only, fragment-packed: element (d,k) at
    //   d*144 + ((k&7)>>1)*32 + ((k>>5)&1)*16 + ((k>>4)&1)*8 + ((k>>3)&1)*4 + (k&1)*2
    for (int idx = tid; idx < 4096; idx += TPB){
        int d = idx >> 6, k = idx & 63;
        float x = W1[idx];
        int ob = d*144 + ((k&7)>>1)*32 + ((k>>5)&1)*16 + ((k>>4)&1)*8 + ((k>>3)&1)*4 + (k&1)*2;
        *(__half*)(sm + W1P + ob) = __float2half_rn(x);
        int o = d*72 + k;
        __half h;
        x = WE[idx];  h = __float2half_rn(x);
        ((__half*)(sm+WEH))[o] = h;  ((__half*)(sm+WEL))[o] = __float2half_rn(x - __half2float(h));
        x = W2a[idx]; h = __float2half_rn(x);
        ((__half*)(sm+W2H))[o] = h;  ((__half*)(sm+W2L))[o] = __float2half_rn(x - __half2float(h));
    }
    if (tid < 64){
        ((float*)(sm+B1O))[tid] = b1[tid];
        ((float*)(sm+B2O))[tid] = b2a[tid];
    }
    __syncthreads();

    int lane = tid & 31, wid = tid >> 5;
    int tig = lane & 3, grp = lane >> 2;        // mma quad layout
    int hi = lane >> 4, lo = lane & 15;         // load map: row parity, float4-in-row

    char* ah = sm + ABUF + wid*AWSZ;            // per-warp A hi halfs (row stride 144B)

    // ---- hoist W1 B-fragments into registers (j-invariant) ----
    unsigned Wb[8][8];
    #pragma unroll
    for (int nt = 0; nt < 8; nt++){
        const char* wb = sm + W1P + (nt*8 + grp)*144 + tig*32;
        uint4 wa = *(const uint4*)(wb);
        uint4 wc = *(const uint4*)(wb + 16);
        Wb[nt][0]=wa.x; Wb[nt][1]=wa.y; Wb[nt][2]=wa.z; Wb[nt][3]=wa.w;
        Wb[nt][4]=wc.x; Wb[nt][5]=wc.y; Wb[nt][6]=wc.z; Wb[nt][7]=wc.w;
    }

    int gw = blockIdx.x*NW + wid;
    int gstride = GRID*NW;
    int ngroups = (nN + 15) >> 4;

    for (int g = gw; g < ngroups; g += gstride){
        int nbase = g*16;
        bool full = (nbase + 16 <= nN);
        // fast-path byte pointers: instr i covers nodes {2i+hi}, this lane's 16B
        const char* bp = (const char*)xn + ((size_t)(nbase + hi))*8192 + lo*16;
        const char* sp = (const char*)xs + ((size_t)(nbase + hi))*256  + lo*16;

        float4 cur[8];
        if (full){
            #pragma unroll
            for (int i = 0; i < 8; i++) cur[i] = *(const float4*)(sp + i*512);
        } else {
            #pragma unroll
            for (int i = 0; i < 8; i++){
                int nd = nbase + 2*i + hi; if (nd >= nN) nd = nN - 1;
                cur[i] = *(const float4*)((const char*)xs + (size_t)nd*256 + lo*16);
            }
        }

        float M[8][4];
        #pragma unroll
        for (int nt = 0; nt < 8; nt++)
            #pragma unroll
            for (int i = 0; i < 4; i++) M[nt][i] = -3.402823466e38f;

        #pragma unroll 1
        for (int j = 0; j < 33; j++){
            // store cur (fp16 hi) into A tile: row = 2i+hi, col4 = lo
            #pragma unroll
            for (int i = 0; i < 8; i++){
                unsigned h0 = pack2(cur[i].x, cur[i].y);
                unsigned h1 = pack2(cur[i].z, cur[i].w);
                *(uint2*)(ah + (2*i + hi)*144 + lo*8) = make_uint2(h0, h1);
            }
            __syncwarp();

            // prefetch neighbor j into same registers (coalesced: 4 lines/instr)
            if (j < 32){
                const char* bj = bp + j*256;
                if (full){
                    #pragma unroll
                    for (int i = 0; i < 8; i++) cur[i] = *(const float4*)(bj + i*16384);
                } else {
                    #pragma unroll
                    for (int i = 0; i < 8; i++){
                        int nd = nbase + 2*i + hi; if (nd >= nN) nd = nN - 1;
                        cur[i] = *(const float4*)((const char*)xn + (size_t)nd*8192 + j*256 + lo*16);
                    }
                }
            }

            // A fragments (hi) for 4 k-tiles
            unsigned Af[4][4];
            #pragma unroll
            for (int kt = 0; kt < 4; kt++){
                int ob = kt*32 + tig*4;
                Af[kt][0] = *(unsigned*)(ah + grp*144     + ob);
                Af[kt][1] = *(unsigned*)(ah + (grp+8)*144 + ob);
                Af[kt][2] = *(unsigned*)(ah + grp*144     + ob + 16);
                Af[kt][3] = *(unsigned*)(ah + (grp+8)*144 + ob + 16);
            }
            __syncwarp();                        // frags read; next STS may proceed

            // single-product: D = Ah * Wh ; W frags from registers
            #pragma unroll
            for (int nt = 0; nt < 8; nt++){
                float D[4] = {0.f, 0.f, 0.f, 0.f};
                mma16816(D, Af[0], Wb[nt][0], Wb[nt][1]);
                mma16816(D, Af[1], Wb[nt][2], Wb[nt][3]);
                mma16816(D, Af[2], Wb[nt][4], Wb[nt][5]);
                mma16816(D, Af[3], Wb[nt][6], Wb[nt][7]);
                M[nt][0] = fmaxf(M[nt][0], D[0]);
                M[nt][1] = fmaxf(M[nt][1], D[1]);
                M[nt][2] = fmaxf(M[nt][2], D[2]);
                M[nt][3] = fmaxf(M[nt][3], D[3]);
            }
        }

        // ---- a = relu(z + b1); frag cols = nt*8 + 2*tig + {0,1} ----
        float av[8][4];
        #pragma unroll
        for (int nt = 0; nt < 8; nt++){
            float2 bb = *(const float2*)(sm + B1O + (nt*8 + 2*tig)*4);
            av[nt][0] = fmaxf(M[nt][0] + bb.x, 0.f);
            av[nt][1] = fmaxf(M[nt][1] + bb.y, 0.f);
            av[nt][2] = fmaxf(M[nt][2] + bb.x, 0.f);
            av[nt][3] = fmaxf(M[nt][3] + bb.y, 0.f);
        }

        // ---- phase B: E = a @ WE^T (frag-chained A, 3-term) ----
        unsigned Fh[4][4], Fl[4][4];
        #pragma unroll
        for (int kt = 0; kt < 4; kt++){
            split2(av[2*kt][0],   av[2*kt][1],   Fh[kt][0], Fl[kt][0]);
            split2(av[2*kt][2],   av[2*kt][3],   Fh[kt][1], Fl[kt][1]);
            split2(av[2*kt+1][0], av[2*kt+1][1], Fh[kt][2], Fl[kt][2]);
            split2(av[2*kt+1][2], av[2*kt+1][3], Fh[kt][3], Fl[kt][3]);
        }
        float E[8][4];
        #pragma unroll
        for (int nt = 0; nt < 8; nt++){
            #pragma unroll
            for (int i = 0; i < 4; i++) E[nt][i] = 0.f;
            int nrow = (nt*8 + grp)*144;
            #pragma unroll
            for (int kt = 0; kt < 4; kt++){
                int ob = nrow + kt*32 + tig*4;
                unsigned bh0 = *(unsigned*)(sm + WEH + ob);
                unsigned bh1 = *(unsigned*)(sm + WEH + ob + 16);
                unsigned bl0 = *(unsigned*)(sm + WEL + ob);
                unsigned bl1 = *(unsigned*)(sm + WEL + ob + 16);
                mma16816(E[nt], Fh[kt], bh0, bh1);
                mma16816(E[nt], Fh[kt], bl0, bl1);
                mma16816(E[nt], Fl[kt], bh0, bh1);
            }
            #pragma unroll
            for (int i = 0; i < 4; i++) E[nt][i] = fmaxf(E[nt][i], 0.f);
        }

        // ---- l2 normalize rows (row grp via c0,c1; row grp+8 via c2,c3) ----
        float s0 = 0.f, s1 = 0.f;
        #pragma unroll
        for (int nt = 0; nt < 8; nt++){
            s0 += E[nt][0]*E[nt][0] + E[nt][1]*E[nt][1];
            s1 += E[nt][2]*E[nt][2] + E[nt][3]*E[nt][3];
        }
        s0 += __shfl_xor_sync(0xffffffffu, s0, 1);
        s0 += __shfl_xor_sync(0xffffffffu, s0, 2);
        s1 += __shfl_xor_sync(0xffffffffu, s1, 1);
        s1 += __shfl_xor_sync(0xffffffffu, s1, 2);
        float i0 = (s0 > 0.f) ? (1.f/sqrtf(s0)) : 0.f;
        float i1 = (s1 > 0.f) ? (1.f/sqrtf(s1)) : 0.f;
        #pragma unroll
        for (int nt = 0; nt < 8; nt++){
            E[nt][0] *= i0; E[nt][1] *= i0;
            E[nt][2] *= i1; E[nt][3] *= i1;
        }

        // ---- phase C: Y = en @ W2^T + b2, relu, reduce + atomic per group ----
        #pragma unroll
        for (int kt = 0; kt < 4; kt++){
            split2(E[2*kt][0],   E[2*kt][1],   Fh[kt][0], Fl[kt][0]);
            split2(E[2*kt][2],   E[2*kt][3],   Fh[kt][1], Fl[kt][1]);
            split2(E[2*kt+1][0], E[2*kt+1][1], Fh[kt][2], Fl[kt][2]);
            split2(E[2*kt+1][2], E[2*kt+1][3], Fh[kt][3], Fl[kt][3]);
        }
        #pragma unroll
        for (int nt = 0; nt < 8; nt++){
            float Y[4] = {0.f, 0.f, 0.f, 0.f};
            int nrow = (nt*8 + grp)*144;
            #pragma unroll
            for (int kt = 0; kt < 4; kt++){
                int ob = nrow + kt*32 + tig*4;
                unsigned bh0 = *(unsigned*)(sm + W2H + ob);
                unsigned bh1 = *(unsigned*)(sm + W2H + ob + 16);
                unsigned bl0 = *(unsigned*)(sm + W2L + ob);
                unsigned bl1 = *(unsigned*)(sm + W2L + ob + 16);
                mma16816(Y, Fh[kt], bh0, bh1);
                mma16816(Y, Fh[kt], bl0, bl1);
                mma16816(Y, Fl[kt], bh0, bh1);
            }
            float2 bb = *(const float2*)(sm + B2O + (nt*8 + 2*tig)*4);
            float y0 = fmaxf(fmaxf(Y[0] + bb.x, 0.f), fmaxf(Y[2] + bb.x, 0.f));
            float y1 = fmaxf(fmaxf(Y[1] + bb.y, 0.f), fmaxf(Y[3] + bb.y, 0.f));
            // reduce node-max across the 8 row-groups (lanes sharing tig)
            #pragma unroll
            for (int off = 4; off < 32; off <<= 1){
                y0 = fmaxf(y0, __shfl_xor_sync(0xffffffffu, y0, off));
                y1 = fmaxf(y1, __shfl_xor_sync(0xffffffffu, y1, off));
            }
            if (grp == 0){
                atomicMax(&g_ymax[nt*8 + 2*tig],     __float_as_uint(y0));
                atomicMax(&g_ymax[nt*8 + 2*tig + 1], __float_as_uint(y1));
            }
        }
        __syncwarp();
    }
}

__global__ void sage_final(const float* __restrict__ E2, const float* __restrict__ RW1,
                           const float* __restrict__ Rb1, const float* __restrict__ RW2,
                           const float* __restrict__ Rb2, float* __restrict__ out)
{
    __shared__ float a2[64], t2[64], hs[64];
    __shared__ float sinv;
    int d = threadIdx.x;
    a2[d] = __uint_as_float(g_ymax[d]);
    __syncthreads();
    float s = 0.f;
    #pragma unroll
    for (int i = 0; i < 64; i++) s += a2[i]*E2[d*64 + i];
    s = fmaxf(s, 0.f);
    t2[d] = s;
    __syncthreads();
    if (d == 0){
        float acc = 0.f;
        for (int i = 0; i < 64; i++) acc += t2[i]*t2[i];
        float nr = sqrtf(acc);
        sinv = (nr > 0.f) ? (1.f/nr) : 0.f;
    }
    __syncthreads();
    a2[d] = t2[d]*sinv;
    __syncthreads();
    float h = Rb1[d];
    #pragma unroll
    for (int i = 0; i < 64; i++) h += a2[i]*RW1[d*64 + i];
    h = fmaxf(h, 0.f);
    hs[d] = h;
    __syncthreads();
    if (d == 0){
        float o = Rb2[0];
        for (int i = 0; i < 64; i++) o += hs[i]*RW2[i];
        out[0] = o;
    }
}

extern "C" void kernel_launch(void* const* d_in, const int* in_sizes, int n_in,
                              void* d_out, int out_size)
{
    const float* xs  = (const float*)d_in[0];
    const float* xn  = (const float*)d_in[1];
    const float* W1  = (const float*)d_in[2];
    const float* b1  = (const float*)d_in[3];
    const float* WE  = (const float*)d_in[4];
    const float* W2a = (const float*)d_in[5];
    const float* b2a = (const float*)d_in[6];
    const float* E2  = (const float*)d_in[7];
    const float* RW1 = (const float*)d_in[8];
    const float* Rb1 = (const float*)d_in[9];
    const float* RW2 = (const float*)d_in[10];
    const float* Rb2 = (const float*)d_in[11];
    int nN = in_sizes[0] / 64;

    cudaFuncSetAttribute(sage_main, cudaFuncAttributeMaxDynamicSharedMemorySize, SMEM_BYTES);
    init_ymax<<<1, 64>>>();
    sage_main<<<GRID, TPB, SMEM_BYTES>>>(xs, xn, W1, b1, WE, W2a, b2a, nN);
    sage_final<<<1, 64>>>(E2, RW1, Rb1, RW2, Rb2, (float*)d_out);
}